// round 4
// baseline (speedup 1.0000x reference)
#include <cuda_runtime.h>
#include <math.h>

#define G   4          // batches per CTA
#define TS  8          // x_seq tile rows per buffer
#define NT  16         // tiles per batch (128/TS)
#define NHH 8
#define DD  512
#define SS  128
#define THREADS 512    // 16 warps

// SMEM float counts
#define XS_F    (2*TS*DD)            // 8192  (double buffer; [0..2047] aliases qs, [4096..6143] aliases xn)
#define QTU_F   (G*NHH*DD)           // 16384 (qt, later reused as u)
#define SCT_F   (NHH*TS)             // 64   per-tile scores/attn
#define FACH_F  8                    // per-head rescale factor / final inv-sum
#define QB_F    (G*NHH)              // 32
#define SMEM_F  (XS_F + QTU_F + SCT_F + FACH_F + QB_F)

__device__ __forceinline__ float warp_sum(float v) {
    v += __shfl_xor_sync(0xffffffffu, v, 16);
    v += __shfl_xor_sync(0xffffffffu, v, 8);
    v += __shfl_xor_sync(0xffffffffu, v, 4);
    v += __shfl_xor_sync(0xffffffffu, v, 2);
    v += __shfl_xor_sync(0xffffffffu, v, 1);
    return v;
}
__device__ __forceinline__ float warp_max(float v) {
    v = fmaxf(v, __shfl_xor_sync(0xffffffffu, v, 16));
    v = fmaxf(v, __shfl_xor_sync(0xffffffffu, v, 8));
    v = fmaxf(v, __shfl_xor_sync(0xffffffffu, v, 4));
    v = fmaxf(v, __shfl_xor_sync(0xffffffffu, v, 2));
    v = fmaxf(v, __shfl_xor_sync(0xffffffffu, v, 1));
    return v;
}

// 4 complete warp sums in 14 shuffles. Returns: every lane holds total of value (lane&3).
__device__ __forceinline__ float reduce4(float a0, float a1, float a2, float a3, int lane) {
    a0 += __shfl_xor_sync(0xffffffffu, a0, 4);
    a0 += __shfl_xor_sync(0xffffffffu, a0, 2);
    a0 += __shfl_xor_sync(0xffffffffu, a0, 1);
    a1 += __shfl_xor_sync(0xffffffffu, a1, 4);
    a1 += __shfl_xor_sync(0xffffffffu, a1, 2);
    a1 += __shfl_xor_sync(0xffffffffu, a1, 1);
    a2 += __shfl_xor_sync(0xffffffffu, a2, 4);
    a2 += __shfl_xor_sync(0xffffffffu, a2, 2);
    a2 += __shfl_xor_sync(0xffffffffu, a2, 1);
    a3 += __shfl_xor_sync(0xffffffffu, a3, 4);
    a3 += __shfl_xor_sync(0xffffffffu, a3, 2);
    a3 += __shfl_xor_sync(0xffffffffu, a3, 1);
    // each lane now holds the aligned-8-group partial (group = lane>>3) for all 4 values
    float v = (lane & 2) ? ((lane & 1) ? a3 : a2) : ((lane & 1) ? a1 : a0);
    // lanes {l, l^8, l^16, l^24} share (l&7) hence the same selected value, one per group
    v += __shfl_xor_sync(0xffffffffu, v, 8);
    v += __shfl_xor_sync(0xffffffffu, v, 16);
    return v;
}

__device__ __forceinline__ void cp16(float4* dst_smem, const float4* src) {
    unsigned int d = (unsigned int)__cvta_generic_to_shared(dst_smem);
    asm volatile("cp.async.cg.shared.global [%0], [%1], 16;\n" :: "r"(d), "l"(src));
}
__device__ __forceinline__ void cp_commit() {
    asm volatile("cp.async.commit_group;\n" ::: "memory");
}
template <int N>
__device__ __forceinline__ void cp_wait() {
    asm volatile("cp.async.wait_group %0;\n" :: "n"(N) : "memory");
}

__global__ __launch_bounds__(THREADS, 2)
void mha_kernel(const float* __restrict__ x_non,
                const float* __restrict__ x_seq,
                const int*   __restrict__ mask,
                const float* __restrict__ Wq, const float* __restrict__ bq,
                const float* __restrict__ Wk, const float* __restrict__ bk,
                const float* __restrict__ Wv, const float* __restrict__ bv,
                float* __restrict__ out)
{
    extern __shared__ float smem[];
    float* xs   = smem;                  // 8192: tile double buffer
    float* qtu  = xs + XS_F;             // 16384: qt, then u
    float* sct  = qtu + QTU_F;           // 64
    float* fach = sct + SCT_F;           // 8
    float* qbs  = fach + FACH_F;         // 32
    // phase-1/2 aliases inside xs (tiles not yet live):
    float* qs = xs;                      // [G][512]
    float* xn = xs + 4096;               // [G][512]

    float4* xs4  = (float4*)xs;
    float4* qtu4 = (float4*)qtu;

    const int tid  = threadIdx.x;
    const int lane = tid & 31;
    const int w    = tid >> 5;           // 0..15
    const int b0   = blockIdx.x * G;

    const int hq  = w >> 3;              // score phase: head quad (0..1)
    const int sl1 = w & 7;               // score phase: tile row (0..7)
    const int hp  = w >> 2;              // u phase: head pair (0..3)
    const int sl2 = w & 3;               // u phase: rows {sl2*2, sl2*2+1}

    // ---- stage x_non ----
    for (int i = tid; i < G*DD; i += THREADS)
        xn[i] = x_non[(size_t)b0*DD + i];
    __syncthreads();

    // ---- phase 1: q[g][i] = Wq[i,:]·xn[g] + bq[i]  (warp w -> rows [w*32, w*32+32)) ----
    {
        const float4* xn4 = (const float4*)xn;
        for (int r = 0; r < 32; r++) {
            const int i = w*32 + r;
            const float4* wrow = (const float4*)(Wq + (size_t)i*DD);
            float a0=0.f, a1=0.f, a2=0.f, a3=0.f;
            #pragma unroll
            for (int m = 0; m < 4; m++) {
                float4 wv = __ldg(wrow + lane + 32*m);
                float4 x0 = xn4[0*128 + lane + 32*m];
                float4 x1 = xn4[1*128 + lane + 32*m];
                float4 x2 = xn4[2*128 + lane + 32*m];
                float4 x3 = xn4[3*128 + lane + 32*m];
                a0 += wv.x*x0.x + wv.y*x0.y + wv.z*x0.z + wv.w*x0.w;
                a1 += wv.x*x1.x + wv.y*x1.y + wv.z*x1.z + wv.w*x1.w;
                a2 += wv.x*x2.x + wv.y*x2.y + wv.z*x2.z + wv.w*x2.w;
                a3 += wv.x*x3.x + wv.y*x3.y + wv.z*x3.z + wv.w*x3.w;
            }
            float v = reduce4(a0, a1, a2, a3, lane);
            float bqi = __ldg(bq + i);
            if (lane < 4) qs[lane*DD + i] = v + bqi;
        }
    }
    __syncthreads();

    // ---- phase 2: qt[g][n][j] = sum_d Wk[n*64+d][j]·q[g][n*64+d] ; qb[g][n] = q·bk_n ----
    {
        for (int idx = tid; idx < NHH*128; idx += THREADS) {   // (n, j4)
            const int n  = idx >> 7;
            const int j4 = idx & 127;
            float4 acc[G];
            #pragma unroll
            for (int g = 0; g < G; g++) acc[g] = make_float4(0.f,0.f,0.f,0.f);
            const float4* wk4 = (const float4*)Wk + (size_t)(n*64)*128 + j4;
            #pragma unroll 4
            for (int d = 0; d < 64; d++) {
                float4 wv = __ldg(wk4 + (size_t)d*128);
                #pragma unroll
                for (int g = 0; g < G; g++) {
                    float qv = qs[g*DD + n*64 + d];
                    acc[g].x += wv.x*qv; acc[g].y += wv.y*qv;
                    acc[g].z += wv.z*qv; acc[g].w += wv.w*qv;
                }
            }
            #pragma unroll
            for (int g = 0; g < G; g++)
                qtu4[g*1024 + idx] = acc[g];
        }
        if (tid < G*NHH) {
            const int gg = tid >> 3, n = tid & 7;
            float s = 0.f;
            for (int d = 0; d < 64; d++) s += qs[gg*DD + n*64 + d] * bk[n*64 + d];
            qbs[tid] = s;
        }
    }
    __syncthreads();   // qs/xn (in xs) dead from here; xs is tile space

    // ---- per-batch attention, single pass with online softmax ----
    for (int g = 0; g < G; g++) {
        const int b = b0 + g;
        const float4* xb4 = (const float4*)(x_seq + (size_t)b * SS * DD);  // 1024 float4 per tile

        float m_run = -INFINITY, s_run = 0.f;   // meaningful for w < 8
        float4 ua0[4], ua1[4];
        #pragma unroll
        for (int m = 0; m < 4; m++) {
            ua0[m] = make_float4(0.f,0.f,0.f,0.f);
            ua1[m] = make_float4(0.f,0.f,0.f,0.f);
        }

        // prime tile 0 into buf0
        cp16(&xs4[tid],       &xb4[tid]);
        cp16(&xs4[tid + 512], &xb4[tid + 512]);
        cp_commit();

        for (int t = 0; t < NT; t++) {
            __syncthreads();                      // (A) prev u-phase done -> safe to overwrite other buf
            if (t + 1 < NT) {
                float4* dst = xs4 + ((t+1)&1)*1024;
                const float4* src = xb4 + (size_t)(t+1)*1024;
                cp16(&dst[tid],       &src[tid]);
                cp16(&dst[tid + 512], &src[tid + 512]);
                cp_commit();
                cp_wait<1>();
            } else {
                cp_wait<0>();
            }
            __syncthreads();                      // (B) tile t visible

            const float* buf = xs + (t&1)*TS*DD;

            // scores: warp (hq, sl1) -> 4 heads, 1 row
            {
                const float4* xr  = (const float4*)(buf + sl1*DD);
                const float4* qt4 = (const float4*)(qtu + g*NHH*DD);
                float a0=0.f, a1=0.f, a2=0.f, a3=0.f;
                #pragma unroll
                for (int m = 0; m < 4; m++) {
                    float4 xv = xr[lane + 32*m];
                    float4 q0 = qt4[(hq*4+0)*128 + lane + 32*m];
                    float4 q1 = qt4[(hq*4+1)*128 + lane + 32*m];
                    float4 q2 = qt4[(hq*4+2)*128 + lane + 32*m];
                    float4 q3 = qt4[(hq*4+3)*128 + lane + 32*m];
                    a0 += xv.x*q0.x + xv.y*q0.y + xv.z*q0.z + xv.w*q0.w;
                    a1 += xv.x*q1.x + xv.y*q1.y + xv.z*q1.z + xv.w*q1.w;
                    a2 += xv.x*q2.x + xv.y*q2.y + xv.z*q2.z + xv.w*q2.w;
                    a3 += xv.x*q3.x + xv.y*q3.y + xv.z*q3.z + xv.w*q3.w;
                }
                float v = reduce4(a0, a1, a2, a3, lane);
                if (lane < 4) {
                    const int h = hq*4 + lane;
                    const int s = t*TS + sl1;
                    const int mk = __ldg(mask + ((size_t)b*NHH + h)*SS + s);
                    float li = mk ? floorf((v + qbs[g*NHH + h]) * 0.125f) : -1e30f;
                    sct[h*TS + sl1] = li;
                }
            }
            __syncthreads();                      // (C) scores ready

            // online softmax update: warp w < 8 owns head w
            if (w < NHH) {
                float li = sct[w*TS + (lane & 7)];       // each s duplicated 4x across warp
                float mt = warp_max(li);
                float mnew = fmaxf(m_run, mt);
                float fac = __expf(m_run - mnew);        // 0 on first tile (m_run = -inf)
                float e   = __expf(li - mnew);
                float stt = warp_sum(e) * 0.25f;         // undo 4x duplication
                s_run = s_run * fac + stt;
                m_run = mnew;
                if (lane < TS) sct[w*TS + lane] = e;
                if (lane == 0) fach[w] = fac;
            }
            __syncthreads();                      // (D) e-weights + factors ready

            // u update: warp (hp, sl2) -> 2 heads, rows {2*sl2, 2*sl2+1}
            {
                const float f0 = fach[hp*2 + 0];
                const float f1 = fach[hp*2 + 1];
                #pragma unroll
                for (int m = 0; m < 4; m++) {
                    ua0[m].x *= f0; ua0[m].y *= f0; ua0[m].z *= f0; ua0[m].w *= f0;
                    ua1[m].x *= f1; ua1[m].y *= f1; ua1[m].z *= f1; ua1[m].w *= f1;
                }
                #pragma unroll
                for (int r = 0; r < 2; r++) {
                    const int row = sl2*2 + r;
                    const float w0 = sct[(hp*2 + 0)*TS + row];
                    const float w1 = sct[(hp*2 + 1)*TS + row];
                    const float4* xr = (const float4*)(buf + row*DD);
                    #pragma unroll
                    for (int m = 0; m < 4; m++) {
                        float4 xv = xr[lane + 32*m];
                        ua0[m].x += w0*xv.x; ua0[m].y += w0*xv.y;
                        ua0[m].z += w0*xv.z; ua0[m].w += w0*xv.w;
                        ua1[m].x += w1*xv.x; ua1[m].y += w1*xv.y;
                        ua1[m].z += w1*xv.z; ua1[m].w += w1*xv.w;
                    }
                }
            }
        } // tiles

        __syncthreads();
        if (w < NHH && lane == 0) fach[w] = 1.0f / s_run;
        __syncthreads();

        // reduce 4 slice-partials into qtu[g] (qt[g] is dead): slice 0 stores, others atomicAdd
        {
            const float inv0 = fach[hp*2 + 0];
            const float inv1 = fach[hp*2 + 1];
            float* ug = qtu + g*NHH*DD;
            if (sl2 == 0) {
                #pragma unroll
                for (int m = 0; m < 4; m++) {
                    float4 v0 = ua0[m], v1 = ua1[m];
                    v0.x*=inv0; v0.y*=inv0; v0.z*=inv0; v0.w*=inv0;
                    v1.x*=inv1; v1.y*=inv1; v1.z*=inv1; v1.w*=inv1;
                    ((float4*)ug)[(hp*2+0)*128 + lane + 32*m] = v0;
                    ((float4*)ug)[(hp*2+1)*128 + lane + 32*m] = v1;
                }
            }
            __syncthreads();
            if (sl2 != 0) {
                #pragma unroll
                for (int m = 0; m < 4; m++) {
                    const int j = (lane + 32*m)*4;
                    atomicAdd(&ug[(hp*2+0)*DD + j + 0], ua0[m].x*inv0);
                    atomicAdd(&ug[(hp*2+0)*DD + j + 1], ua0[m].y*inv0);
                    atomicAdd(&ug[(hp*2+0)*DD + j + 2], ua0[m].z*inv0);
                    atomicAdd(&ug[(hp*2+0)*DD + j + 3], ua0[m].w*inv0);
                    atomicAdd(&ug[(hp*2+1)*DD + j + 0], ua1[m].x*inv1);
                    atomicAdd(&ug[(hp*2+1)*DD + j + 1], ua1[m].y*inv1);
                    atomicAdd(&ug[(hp*2+1)*DD + j + 2], ua1[m].z*inv1);
                    atomicAdd(&ug[(hp*2+1)*DD + j + 3], ua1[m].w*inv1);
                }
            }
            __syncthreads();
        }
    } // batches

    // ---- phase z: out[b_g][i] = Wv[i,:]·u[g][head(i)] + bv[i]  (warp w -> rows [w*32, w*32+32)) ----
    {
        const int zn = w >> 1;   // head for this warp's rows
        for (int r = 0; r < 32; r++) {
            const int i = w*32 + r;
            const float4* wrow = (const float4*)(Wv + (size_t)i*DD);
            float a0=0.f, a1=0.f, a2=0.f, a3=0.f;
            #pragma unroll
            for (int m = 0; m < 4; m++) {
                float4 wv = __ldg(wrow + lane + 32*m);
                float4 u0 = qtu4[0*1024 + zn*128 + lane + 32*m];
                float4 u1 = qtu4[1*1024 + zn*128 + lane + 32*m];
                float4 u2 = qtu4[2*1024 + zn*128 + lane + 32*m];
                float4 u3 = qtu4[3*1024 + zn*128 + lane + 32*m];
                a0 += wv.x*u0.x + wv.y*u0.y + wv.z*u0.z + wv.w*u0.w;
                a1 += wv.x*u1.x + wv.y*u1.y + wv.z*u1.z + wv.w*u1.w;
                a2 += wv.x*u2.x + wv.y*u2.y + wv.z*u2.z + wv.w*u2.w;
                a3 += wv.x*u3.x + wv.y*u3.y + wv.z*u3.z + wv.w*u3.w;
            }
            float v = reduce4(a0, a1, a2, a3, lane);
            float bvi = __ldg(bv + i);
            if (lane < 4)
                out[(size_t)(b0 + lane)*DD + i] = v + bvi;
        }
    }
}

extern "C" void kernel_launch(void* const* d_in, const int* in_sizes, int n_in,
                              void* d_out, int out_size)
{
    const float* x_non = (const float*)d_in[0];
    const float* x_seq = (const float*)d_in[1];
    const int*   mask  = (const int*)  d_in[2];
    const float* Wq    = (const float*)d_in[3];
    const float* bq    = (const float*)d_in[4];
    const float* Wk    = (const float*)d_in[5];
    const float* bk    = (const float*)d_in[6];
    const float* Wv    = (const float*)d_in[7];
    const float* bv    = (const float*)d_in[8];
    float* out = (float*)d_out;

    const int smem_bytes = SMEM_F * (int)sizeof(float);   // ~97 KB -> 2 CTAs/SM
    cudaFuncSetAttribute(mha_kernel, cudaFuncAttributeMaxDynamicSharedMemorySize, smem_bytes);
    mha_kernel<<<1024/G, THREADS, smem_bytes>>>(x_non, x_seq, mask,
                                                Wq, bq, Wk, bk, Wv, bv, out);
}

// round 5
// speedup vs baseline: 1.0682x; 1.0682x over previous
#include <cuda_runtime.h>
#include <math.h>

#define G   4          // batches per CTA
#define TS  16         // x_seq tile rows per buffer
#define NT  8          // tiles per batch (128/TS)
#define NHH 8
#define DD  512
#define SS  128
#define THREADS 1024   // 32 warps

// SMEM float counts
#define XS_F    (2*TS*DD)            // 16384 (double buffer)
#define QTU_F   (G*NHH*DD)           // 16384 (qt, later reused as u)
#define QS_F    (G*DD)               // 2048
#define SC_F    (G*NHH*SS)           // 4096  (scores -> attn; also x_non staging)
#define QB_F    (G*NHH)              // 32
#define SMEM_F  (XS_F + QTU_F + QS_F + SC_F + QB_F)   // 38944 fl ~152 KB

__device__ __forceinline__ float warp_sum(float v) {
    v += __shfl_xor_sync(0xffffffffu, v, 16);
    v += __shfl_xor_sync(0xffffffffu, v, 8);
    v += __shfl_xor_sync(0xffffffffu, v, 4);
    v += __shfl_xor_sync(0xffffffffu, v, 2);
    v += __shfl_xor_sync(0xffffffffu, v, 1);
    return v;
}
__device__ __forceinline__ float warp_max(float v) {
    v = fmaxf(v, __shfl_xor_sync(0xffffffffu, v, 16));
    v = fmaxf(v, __shfl_xor_sync(0xffffffffu, v, 8));
    v = fmaxf(v, __shfl_xor_sync(0xffffffffu, v, 4));
    v = fmaxf(v, __shfl_xor_sync(0xffffffffu, v, 2));
    v = fmaxf(v, __shfl_xor_sync(0xffffffffu, v, 1));
    return v;
}

// 4 complete warp sums in 14 shuffles. Every lane returns total of value (lane&3).
__device__ __forceinline__ float reduce4(float a0, float a1, float a2, float a3, int lane) {
    a0 += __shfl_xor_sync(0xffffffffu, a0, 4);
    a1 += __shfl_xor_sync(0xffffffffu, a1, 4);
    a2 += __shfl_xor_sync(0xffffffffu, a2, 4);
    a3 += __shfl_xor_sync(0xffffffffu, a3, 4);
    a0 += __shfl_xor_sync(0xffffffffu, a0, 2);
    a1 += __shfl_xor_sync(0xffffffffu, a1, 2);
    a2 += __shfl_xor_sync(0xffffffffu, a2, 2);
    a3 += __shfl_xor_sync(0xffffffffu, a3, 2);
    a0 += __shfl_xor_sync(0xffffffffu, a0, 1);
    a1 += __shfl_xor_sync(0xffffffffu, a1, 1);
    a2 += __shfl_xor_sync(0xffffffffu, a2, 1);
    a3 += __shfl_xor_sync(0xffffffffu, a3, 1);
    float v = (lane & 2) ? ((lane & 1) ? a3 : a2) : ((lane & 1) ? a1 : a0);
    v += __shfl_xor_sync(0xffffffffu, v, 8);
    v += __shfl_xor_sync(0xffffffffu, v, 16);
    return v;
}

__device__ __forceinline__ void cp16(float4* dst_smem, const float4* src) {
    unsigned int d = (unsigned int)__cvta_generic_to_shared(dst_smem);
    asm volatile("cp.async.cg.shared.global [%0], [%1], 16;\n" :: "r"(d), "l"(src));
}
__device__ __forceinline__ void cp_commit() {
    asm volatile("cp.async.commit_group;\n" ::: "memory");
}
template <int N>
__device__ __forceinline__ void cp_wait() {
    asm volatile("cp.async.wait_group %0;\n" :: "n"(N) : "memory");
}

__global__ __launch_bounds__(THREADS, 1)
void mha_kernel(const float* __restrict__ x_non,
                const float* __restrict__ x_seq,
                const int*   __restrict__ mask,
                const float* __restrict__ Wq, const float* __restrict__ bq,
                const float* __restrict__ Wk, const float* __restrict__ bk,
                const float* __restrict__ Wv, const float* __restrict__ bv,
                float* __restrict__ out)
{
    extern __shared__ float smem[];
    float* xs  = smem;                 // 2 x [TS][512]
    float* qtu = xs + XS_F;            // [G][8][512]  qt then u
    float* qs  = qtu + QTU_F;          // [G][512]
    float* sc  = qs + QS_F;            // [G][8][128]  scores/attn (and x_non staging)
    float* qb  = sc + SC_F;            // [G][8]

    float4* xs4  = (float4*)xs;
    float4* qtu4 = (float4*)qtu;

    const int tid  = threadIdx.x;
    const int lane = tid & 31;
    const int w    = tid >> 5;         // 0..31
    const int b0   = blockIdx.x * G;

    // attention mapping: warp = (head pair, s-slice of 2 rows)
    const int hp = w >> 3;             // 0..3 -> heads {2hp, 2hp+1}
    const int sl = w & 7;              // rows {sl*2, sl*2+1} of 16-row tile
    const int h0 = hp * 2;

    // ---- stage x_non into sc region ----
    for (int i = tid; i < G*DD; i += THREADS)
        sc[i] = x_non[(size_t)b0*DD + i];
    __syncthreads();

    // ---- phase 1: q[g][i] = Wq[i,:]·xn[g] + bq[i]  (warp w -> rows [w*16, w*16+16)) ----
    {
        const float4* xn4 = (const float4*)sc;
        for (int r = 0; r < 16; r++) {
            const int i = w*16 + r;
            const float4* wrow = (const float4*)(Wq + (size_t)i*DD);
            float a0=0.f, a1=0.f, a2=0.f, a3=0.f;
            #pragma unroll
            for (int m = 0; m < 4; m++) {
                float4 wv = __ldg(wrow + lane + 32*m);
                float4 x0 = xn4[0*128 + lane + 32*m];
                float4 x1 = xn4[1*128 + lane + 32*m];
                float4 x2 = xn4[2*128 + lane + 32*m];
                float4 x3 = xn4[3*128 + lane + 32*m];
                a0 += wv.x*x0.x + wv.y*x0.y + wv.z*x0.z + wv.w*x0.w;
                a1 += wv.x*x1.x + wv.y*x1.y + wv.z*x1.z + wv.w*x1.w;
                a2 += wv.x*x2.x + wv.y*x2.y + wv.z*x2.z + wv.w*x2.w;
                a3 += wv.x*x3.x + wv.y*x3.y + wv.z*x3.z + wv.w*x3.w;
            }
            float v = reduce4(a0, a1, a2, a3, lane);
            float bqi = __ldg(bq + i);
            if (lane < 4) qs[lane*DD + i] = v + bqi;
        }
    }
    __syncthreads();

    // ---- phase 2: qt[g][n][j] = sum_d Wk[n*64+d][j]·q[g][n*64+d] ; qb[g][n] = q·bk_n ----
    {
        // exactly one (n, j4) per thread: 8*128 = 1024
        const int n  = tid >> 7;
        const int j4 = tid & 127;
        float4 acc[G];
        #pragma unroll
        for (int g = 0; g < G; g++) acc[g] = make_float4(0.f,0.f,0.f,0.f);
        const float4* wk4 = (const float4*)Wk + (size_t)(n*64)*128 + j4;
        #pragma unroll 4
        for (int d = 0; d < 64; d++) {
            float4 wv = __ldg(wk4 + (size_t)d*128);
            #pragma unroll
            for (int g = 0; g < G; g++) {
                float qv = qs[g*DD + n*64 + d];
                acc[g].x += wv.x*qv; acc[g].y += wv.y*qv;
                acc[g].z += wv.z*qv; acc[g].w += wv.w*qv;
            }
        }
        #pragma unroll
        for (int g = 0; g < G; g++)
            qtu4[g*1024 + tid] = acc[g];

        if (tid < G*NHH) {
            const int gg = tid >> 3, nn = tid & 7;
            float s = 0.f;
            for (int d = 0; d < 64; d++) s += qs[gg*DD + nn*64 + d] * bk[nn*64 + d];
            qb[tid] = s;
        }
    }
    __syncthreads();

    // ---- per-batch attention (two passes) ----
    for (int g = 0; g < G; g++) {
        const int b = b0 + g;
        const float4* xb4 = (const float4*)(x_seq + (size_t)b * SS * DD);  // 2048 float4/tile

        // cache qt lane slices for this warp's 2 heads
        float4 qtr0[4], qtr1[4];
        #pragma unroll
        for (int m = 0; m < 4; m++) {
            qtr0[m] = qtu4[g*1024 + (h0+0)*128 + lane + 32*m];
            qtr1[m] = qtu4[g*1024 + (h0+1)*128 + lane + 32*m];
        }

        // prime tile 0 into buf0
        cp16(&xs4[tid],        &xb4[tid]);
        cp16(&xs4[tid + 1024], &xb4[tid + 1024]);
        cp_commit();

        // ---- pass 1: raw scores ----
        for (int t = 0; t < NT; t++) {
            __syncthreads();   // prev readers of buf[(t+1)&1] done
            if (t + 1 < NT) {
                float4* dst = xs4 + ((t+1)&1)*2048;
                const float4* src = xb4 + (size_t)(t+1)*2048;
                cp16(&dst[tid],        &src[tid]);
                cp16(&dst[tid + 1024], &src[tid + 1024]);
                cp_commit();
                cp_wait<1>();
            } else {
                cp_wait<0>();
            }
            __syncthreads();   // tile t visible

            const float* buf = xs + (t&1)*TS*DD;
            const float4* xr0 = (const float4*)(buf + (sl*2+0)*DD);
            const float4* xr1 = (const float4*)(buf + (sl*2+1)*DD);
            float a0=0.f, a1=0.f, a2=0.f, a3=0.f;   // (h0,r0)(h0,r1)(h1,r0)(h1,r1)
            #pragma unroll
            for (int m = 0; m < 4; m++) {
                float4 x0 = xr0[lane + 32*m];
                float4 x1 = xr1[lane + 32*m];
                a0 += x0.x*qtr0[m].x + x0.y*qtr0[m].y + x0.z*qtr0[m].z + x0.w*qtr0[m].w;
                a1 += x1.x*qtr0[m].x + x1.y*qtr0[m].y + x1.z*qtr0[m].z + x1.w*qtr0[m].w;
                a2 += x0.x*qtr1[m].x + x0.y*qtr1[m].y + x0.z*qtr1[m].z + x0.w*qtr1[m].w;
                a3 += x1.x*qtr1[m].x + x1.y*qtr1[m].y + x1.z*qtr1[m].z + x1.w*qtr1[m].w;
            }
            float v = reduce4(a0, a1, a2, a3, lane);
            if (lane < 4) {
                const int h   = h0 + (lane >> 1);
                const int row = sl*2 + (lane & 1);
                sc[g*1024 + h*SS + t*TS + row] = v;
            }
        }
        __syncthreads();

        // ---- softmax (warps 0..7, warp w -> head w) ----
        if (w < NHH) {
            const int* mrow = mask + ((size_t)b*NHH + w)*SS;
            const float qbb = qb[g*NHH + w];
            float l[4];
            #pragma unroll
            for (int k = 0; k < 4; k++) {
                const int s = lane + 32*k;
                float raw = sc[g*1024 + w*SS + s] + qbb;
                l[k] = (mrow[s] != 0) ? floorf(raw * 0.125f) : -1e30f;
            }
            float mx = fmaxf(fmaxf(l[0],l[1]), fmaxf(l[2],l[3]));
            mx = warp_max(mx);
            float e[4]; float ssum = 0.f;
            #pragma unroll
            for (int k = 0; k < 4; k++) { e[k] = expf(l[k] - mx); ssum += e[k]; }
            ssum = warp_sum(ssum);
            const float inv = 1.0f / ssum;
            #pragma unroll
            for (int k = 0; k < 4; k++)
                sc[g*1024 + w*SS + lane + 32*k] = e[k] * inv;
        }
        __syncthreads();

        // ---- pass 2 (reverse tiles; 7 and 6 still resident) ----
        {
            float4 ua0[4], ua1[4];
            #pragma unroll
            for (int m = 0; m < 4; m++) {
                ua0[m] = make_float4(0.f,0.f,0.f,0.f);
                ua1[m] = make_float4(0.f,0.f,0.f,0.f);
            }
            for (int t = NT-1; t >= 0; t--) {
                if (t <= NT-3) {              // prefetched tile: wait for it
                    if (t > 0) cp_wait<1>(); else cp_wait<0>();
                    __syncthreads();
                }
                const float* buf = xs + (t&1)*TS*DD;
                const int r0 = sl*2 + 0, r1 = sl*2 + 1;
                const float w00 = sc[g*1024 + (h0+0)*SS + t*TS + r0];
                const float w01 = sc[g*1024 + (h0+0)*SS + t*TS + r1];
                const float w10 = sc[g*1024 + (h0+1)*SS + t*TS + r0];
                const float w11 = sc[g*1024 + (h0+1)*SS + t*TS + r1];
                const float4* xr0 = (const float4*)(buf + r0*DD);
                const float4* xr1 = (const float4*)(buf + r1*DD);
                #pragma unroll
                for (int m = 0; m < 4; m++) {
                    float4 x0 = xr0[lane + 32*m];
                    float4 x1 = xr1[lane + 32*m];
                    ua0[m].x += w00*x0.x + w01*x1.x;
                    ua0[m].y += w00*x0.y + w01*x1.y;
                    ua0[m].z += w00*x0.z + w01*x1.z;
                    ua0[m].w += w00*x0.w + w01*x1.w;
                    ua1[m].x += w10*x0.x + w11*x1.x;
                    ua1[m].y += w10*x0.y + w11*x1.y;
                    ua1[m].z += w10*x0.z + w11*x1.z;
                    ua1[m].w += w10*x0.w + w11*x1.w;
                }
                __syncthreads();    // done reading buf[t&1]
                if (t - 2 >= 0) {   // prefetch tile t-2 into freed buffer
                    float4* dst = xs4 + (t&1)*2048;
                    const float4* src = xb4 + (size_t)(t-2)*2048;
                    cp16(&dst[tid],        &src[tid]);
                    cp16(&dst[tid + 1024], &src[tid + 1024]);
                    cp_commit();
                }
            }

            // reduce 8 slice-partials into qtu[g] (qt[g] now dead): sl==0 stores, rest atomicAdd
            float* ug = qtu + g*NHH*DD;
            if (sl == 0) {
                #pragma unroll
                for (int m = 0; m < 4; m++) {
                    ((float4*)ug)[(h0+0)*128 + lane + 32*m] = ua0[m];
                    ((float4*)ug)[(h0+1)*128 + lane + 32*m] = ua1[m];
                }
            }
            __syncthreads();
            if (sl != 0) {
                #pragma unroll
                for (int m = 0; m < 4; m++) {
                    const int j = (lane + 32*m)*4;
                    atomicAdd(&ug[(h0+0)*DD + j + 0], ua0[m].x);
                    atomicAdd(&ug[(h0+0)*DD + j + 1], ua0[m].y);
                    atomicAdd(&ug[(h0+0)*DD + j + 2], ua0[m].z);
                    atomicAdd(&ug[(h0+0)*DD + j + 3], ua0[m].w);
                    atomicAdd(&ug[(h0+1)*DD + j + 0], ua1[m].x);
                    atomicAdd(&ug[(h0+1)*DD + j + 1], ua1[m].y);
                    atomicAdd(&ug[(h0+1)*DD + j + 2], ua1[m].z);
                    atomicAdd(&ug[(h0+1)*DD + j + 3], ua1[m].w);
                }
            }
            __syncthreads();
        }
    } // batches

    // ---- phase z: out[b_g][i] = Wv[i,:]·u[g][head(i)] + bv[i]  (warp w -> rows [w*16, w*16+16)) ----
    {
        const int zn = w >> 2;   // head for this warp's 16 rows
        for (int r = 0; r < 16; r++) {
            const int i = w*16 + r;
            const float4* wrow = (const float4*)(Wv + (size_t)i*DD);
            float a0=0.f, a1=0.f, a2=0.f, a3=0.f;
            #pragma unroll
            for (int m = 0; m < 4; m++) {
                float4 wv = __ldg(wrow + lane + 32*m);
                float4 u0 = qtu4[0*1024 + zn*128 + lane + 32*m];
                float4 u1 = qtu4[1*1024 + zn*128 + lane + 32*m];
                float4 u2 = qtu4[2*1024 + zn*128 + lane + 32*m];
                float4 u3 = qtu4[3*1024 + zn*128 + lane + 32*m];
                a0 += wv.x*u0.x + wv.y*u0.y + wv.z*u0.z + wv.w*u0.w;
                a1 += wv.x*u1.x + wv.y*u1.y + wv.z*u1.z + wv.w*u1.w;
                a2 += wv.x*u2.x + wv.y*u2.y + wv.z*u2.z + wv.w*u2.w;
                a3 += wv.x*u3.x + wv.y*u3.y + wv.z*u3.z + wv.w*u3.w;
            }
            float v = reduce4(a0, a1, a2, a3, lane);
            float bvi = __ldg(bv + i);
            if (lane < 4)
                out[(size_t)(b0 + lane)*DD + i] = v + bvi;
        }
    }
}

extern "C" void kernel_launch(void* const* d_in, const int* in_sizes, int n_in,
                              void* d_out, int out_size)
{
    const float* x_non = (const float*)d_in[0];
    const float* x_seq = (const float*)d_in[1];
    const int*   mask  = (const int*)  d_in[2];
    const float* Wq    = (const float*)d_in[3];
    const float* bq    = (const float*)d_in[4];
    const float* Wk    = (const float*)d_in[5];
    const float* bk    = (const float*)d_in[6];
    const float* Wv    = (const float*)d_in[7];
    const float* bv    = (const float*)d_in[8];
    float* out = (float*)d_out;

    const int smem_bytes = SMEM_F * (int)sizeof(float);   // ~152 KB
    cudaFuncSetAttribute(mha_kernel, cudaFuncAttributeMaxDynamicSharedMemorySize, smem_bytes);
    mha_kernel<<<1024/G, THREADS, smem_bytes>>>(x_non, x_seq, mask,
                                                Wq, bq, Wk, bk, Wv, bv, out);
}

// round 7
// speedup vs baseline: 1.4481x; 1.3557x over previous
#include <cuda_runtime.h>
#include <math.h>

#define G   4          // batches per CTA
#define TS  16         // x_seq tile rows per buffer
#define NT  8          // tiles per batch (128/TS)
#define NHH 8
#define DD  512
#define SS  128
#define THREADS 512    // 16 warps

// SMEM float counts
#define BUF_F   (TS*DD)              // 8192 per buffer
#define XS_F    (2*BUF_F)            // 16384 (double buffer; also pass-2 partial scratch)
#define QTU_F   (G*NHH*DD)           // 16384  (qt, later reused as u)
#define QS_F    (G*DD)               // 2048
#define SC_F    (G*NHH*SS)           // 4096   (scores -> attn; also x_non staging)
#define QB_F    (G*NHH)              // 32
#define SMEM_F  (XS_F + QTU_F + QS_F + SC_F + QB_F)

typedef unsigned long long u64;
typedef ulonglong2 u64x2;

// packed f32x2 fused multiply-add: d = a*b + c elementwise on (lo,hi) pairs
__device__ __forceinline__ u64 ffma2(u64 a, u64 b, u64 c) {
    u64 d;
    asm("fma.rn.f32x2 %0, %1, %2, %3;" : "=l"(d) : "l"(a), "l"(b), "l"(c));
    return d;
}
__device__ __forceinline__ u64 pack2(float lo, float hi) {
    u64 d; asm("mov.b64 %0, {%1, %2};" : "=l"(d) : "f"(lo), "f"(hi)); return d;
}
__device__ __forceinline__ float hsum2(u64 a) {
    float lo, hi;
    asm("mov.b64 {%0, %1}, %2;" : "=f"(lo), "=f"(hi) : "l"(a));
    return lo + hi;
}

__device__ __forceinline__ float warp_sum(float v) {
    v += __shfl_xor_sync(0xffffffffu, v, 16);
    v += __shfl_xor_sync(0xffffffffu, v, 8);
    v += __shfl_xor_sync(0xffffffffu, v, 4);
    v += __shfl_xor_sync(0xffffffffu, v, 2);
    v += __shfl_xor_sync(0xffffffffu, v, 1);
    return v;
}
__device__ __forceinline__ float warp_max(float v) {
    v = fmaxf(v, __shfl_xor_sync(0xffffffffu, v, 16));
    v = fmaxf(v, __shfl_xor_sync(0xffffffffu, v, 8));
    v = fmaxf(v, __shfl_xor_sync(0xffffffffu, v, 4));
    v = fmaxf(v, __shfl_xor_sync(0xffffffffu, v, 2));
    v = fmaxf(v, __shfl_xor_sync(0xffffffffu, v, 1));
    return v;
}

// 4 complete warp sums in 14 shuffles. Every lane returns total of value (lane&3).
__device__ __forceinline__ float reduce4(float a0, float a1, float a2, float a3, int lane) {
    a0 += __shfl_xor_sync(0xffffffffu, a0, 4);
    a1 += __shfl_xor_sync(0xffffffffu, a1, 4);
    a2 += __shfl_xor_sync(0xffffffffu, a2, 4);
    a3 += __shfl_xor_sync(0xffffffffu, a3, 4);
    a0 += __shfl_xor_sync(0xffffffffu, a0, 2);
    a1 += __shfl_xor_sync(0xffffffffu, a1, 2);
    a2 += __shfl_xor_sync(0xffffffffu, a2, 2);
    a3 += __shfl_xor_sync(0xffffffffu, a3, 2);
    a0 += __shfl_xor_sync(0xffffffffu, a0, 1);
    a1 += __shfl_xor_sync(0xffffffffu, a1, 1);
    a2 += __shfl_xor_sync(0xffffffffu, a2, 1);
    a3 += __shfl_xor_sync(0xffffffffu, a3, 1);
    float v = (lane & 2) ? ((lane & 1) ? a3 : a2) : ((lane & 1) ? a1 : a0);
    v += __shfl_xor_sync(0xffffffffu, v, 8);
    v += __shfl_xor_sync(0xffffffffu, v, 16);
    return v;
}

__device__ __forceinline__ void cp16(float4* dst_smem, const float4* src) {
    unsigned int d = (unsigned int)__cvta_generic_to_shared(dst_smem);
    asm volatile("cp.async.cg.shared.global [%0], [%1], 16;\n" :: "r"(d), "l"(src));
}
__device__ __forceinline__ void cp_commit() {
    asm volatile("cp.async.commit_group;\n" ::: "memory");
}
template <int N>
__device__ __forceinline__ void cp_wait() {
    asm volatile("cp.async.wait_group %0;\n" :: "n"(N) : "memory");
}

__global__ __launch_bounds__(THREADS, 1)
void mha_kernel(const float* __restrict__ x_non,
                const float* __restrict__ x_seq,
                const int*   __restrict__ mask,
                const float* __restrict__ Wq, const float* __restrict__ bq,
                const float* __restrict__ Wk, const float* __restrict__ bk,
                const float* __restrict__ Wv, const float* __restrict__ bv,
                float* __restrict__ out)
{
    extern __shared__ float smem[];
    float* xs  = smem;                 // 2 x [TS][512]; later [4][8][512] partial-u scratch
    float* qtu = xs + XS_F;            // [G][8][512]  qt then u
    float* qs  = qtu + QTU_F;          // [G][512]
    float* sc  = qs + QS_F;            // [G][8][128]  scores/attn (and x_non staging)
    float* qb  = sc + SC_F;            // [G][8]

    float4* xs4  = (float4*)xs;
    float4* qtu4 = (float4*)qtu;
    u64x2*  qtu2 = (u64x2*)qtu;

    const int tid  = threadIdx.x;
    const int lane = tid & 31;
    const int w    = tid >> 5;         // 0..15
    const int b0   = blockIdx.x * G;

    // pass-1 mapping: head quad + s-slice of 2 rows
    const int hq  = w >> 3;            // 0..1 -> heads hq*4 .. hq*4+3
    const int sl1 = w & 7;             // rows {sl1*2, sl1*2+1} of tile
    // pass-2 mapping: head pair + s-slice of 4 rows
    const int hp  = w >> 2;            // 0..3 -> heads hp*2, hp*2+1
    const int sl2 = w & 3;             // rows [sl2*4, sl2*4+4) of tile

    // ---- stage x_non[b0..b0+G) into sc region ----
    for (int i = tid; i < G*DD; i += THREADS)
        sc[i] = x_non[(size_t)b0*DD + i];
    __syncthreads();

    // ---- phase 1: q[g][i] = Wq[i,:]·xn[g] + bq[i]  (warp w -> rows [w*32, w*32+32)) ----
    {
        const u64x2* xn2 = (const u64x2*)sc;
        u64x2 xr[G][4];
        #pragma unroll
        for (int g = 0; g < G; g++)
            #pragma unroll
            for (int m = 0; m < 4; m++)
                xr[g][m] = xn2[g*128 + lane + 32*m];

        for (int r = 0; r < 32; r++) {
            const int i = w*32 + r;
            const u64x2* wrow = (const u64x2*)(Wq + (size_t)i*DD);
            u64 acc[G] = {0ull, 0ull, 0ull, 0ull};
            #pragma unroll
            for (int m = 0; m < 4; m++) {
                u64x2 wv = wrow[lane + 32*m];
                #pragma unroll
                for (int g = 0; g < G; g++) {
                    acc[g] = ffma2(wv.x, xr[g][m].x, acc[g]);
                    acc[g] = ffma2(wv.y, xr[g][m].y, acc[g]);
                }
            }
            float v = reduce4(hsum2(acc[0]), hsum2(acc[1]), hsum2(acc[2]), hsum2(acc[3]), lane);
            float bqi = __ldg(bq + i);
            if (lane < 4) qs[lane*DD + i] = v + bqi;
        }
    }
    __syncthreads();

    // ---- phase 2: qt[g][n][j] = sum_d Wk[n*64+d][j]·q[g][n*64+d] ; qb[g][n] = q·bk_n ----
    {
        for (int idx = tid; idx < NHH*128; idx += THREADS) {   // (n, j4)
            const int n  = idx >> 7;
            const int j4 = idx & 127;
            u64 acc[G][2];
            #pragma unroll
            for (int g = 0; g < G; g++) { acc[g][0] = 0ull; acc[g][1] = 0ull; }
            const u64x2* wk2 = (const u64x2*)Wk + (size_t)(n*64)*128 + j4;
            #pragma unroll 4
            for (int d = 0; d < 64; d++) {
                u64x2 wv = wk2[(size_t)d*128];
                #pragma unroll
                for (int g = 0; g < G; g++) {
                    float qv = qs[g*DD + n*64 + d];
                    u64 qp = pack2(qv, qv);
                    acc[g][0] = ffma2(wv.x, qp, acc[g][0]);
                    acc[g][1] = ffma2(wv.y, qp, acc[g][1]);
                }
            }
            #pragma unroll
            for (int g = 0; g < G; g++) {
                u64x2 t; t.x = acc[g][0]; t.y = acc[g][1];
                qtu2[g*1024 + idx] = t;
            }
        }
        if (tid < G*NHH) {
            const int gg = tid >> 3, n = tid & 7;
            float s = 0.f;
            for (int d = 0; d < 64; d++) s += qs[gg*DD + n*64 + d] * bk[n*64 + d];
            qb[tid] = s;
        }
    }
    __syncthreads();

    // ---- per-batch attention (two passes) ----
    for (int g = 0; g < G; g++) {
        const int b = b0 + g;
        const float4* xb4 = (const float4*)(x_seq + (size_t)b * SS * DD);  // 2048 float4/tile

        // hoist qt lane slices for this warp's 4 heads (pass-1), packed
        u64x2 qtr[4][4];
        #pragma unroll
        for (int h = 0; h < 4; h++)
            #pragma unroll
            for (int m = 0; m < 4; m++)
                qtr[h][m] = qtu2[g*1024 + (hq*4+h)*128 + lane + 32*m];

        // prime tile 0 into buf0
        {
            #pragma unroll
            for (int i = 0; i < 4; i++) cp16(&xs4[tid + 512*i], &xb4[tid + 512*i]);
            cp_commit();
        }

        // ---- pass 1: raw scores (bias added in softmax) ----
        for (int t = 0; t < NT; t++) {
            __syncthreads();   // everyone done with buf[(t+1)&1]'s old contents
            if (t + 1 < NT) {
                float4* dst = xs4 + ((t+1)&1)*2048;
                const float4* src = xb4 + (size_t)(t+1)*2048;
                #pragma unroll
                for (int i = 0; i < 4; i++) cp16(&dst[tid + 512*i], &src[tid + 512*i]);
                cp_commit();
                cp_wait<1>();
            } else {
                cp_wait<0>();
            }
            __syncthreads();   // tile t visible to all

            const float* buf = xs + (t&1)*BUF_F;
            #pragma unroll 2
            for (int r = 0; r < 2; r++) {
                const int srow = sl1*2 + r;
                const u64x2* xr = (const u64x2*)(buf + srow*DD);
                u64 a0 = 0ull, a1 = 0ull, a2 = 0ull, a3 = 0ull;
                #pragma unroll
                for (int m = 0; m < 4; m++) {
                    u64x2 xv = xr[lane + 32*m];
                    a0 = ffma2(xv.x, qtr[0][m].x, a0);
                    a0 = ffma2(xv.y, qtr[0][m].y, a0);
                    a1 = ffma2(xv.x, qtr[1][m].x, a1);
                    a1 = ffma2(xv.y, qtr[1][m].y, a1);
                    a2 = ffma2(xv.x, qtr[2][m].x, a2);
                    a2 = ffma2(xv.y, qtr[2][m].y, a2);
                    a3 = ffma2(xv.x, qtr[3][m].x, a3);
                    a3 = ffma2(xv.y, qtr[3][m].y, a3);
                }
                float v = reduce4(hsum2(a0), hsum2(a1), hsum2(a2), hsum2(a3), lane);
                if (lane < 4) {
                    const int s = t*TS + srow;
                    sc[g*1024 + (hq*4 + lane)*SS + s] = v;
                }
            }
        }
        __syncthreads();

        // ---- softmax (warps 0..7, warp w -> head w) ----
        if (w < NHH) {
            const int* mrow = mask + ((size_t)b*NHH + w)*SS;
            const float qbb = qb[g*NHH + w];
            float l[4];
            #pragma unroll
            for (int k = 0; k < 4; k++) {
                const int s = lane + 32*k;
                float raw = sc[g*1024 + w*SS + s] + qbb;
                l[k] = (mrow[s] != 0) ? floorf(raw * 0.125f) : -1e30f;
            }
            float mx = fmaxf(fmaxf(l[0],l[1]), fmaxf(l[2],l[3]));
            mx = warp_max(mx);
            float e[4]; float ssum = 0.f;
            #pragma unroll
            for (int k = 0; k < 4; k++) { e[k] = expf(l[k] - mx); ssum += e[k]; }
            ssum = warp_sum(ssum);
            const float inv = 1.0f / ssum;
            #pragma unroll
            for (int k = 0; k < 4; k++)
                sc[g*1024 + w*SS + lane + 32*k] = e[k] * inv;
        }
        __syncthreads();

        // ---- pass 2 (reverse tiles; 7 and 6 still resident from pass 1) ----
        {
            const int h0 = hp*2;
            u64 ua0[8], ua1[8];
            #pragma unroll
            for (int m = 0; m < 8; m++) { ua0[m] = 0ull; ua1[m] = 0ull; }

            for (int t = NT-1; t >= 0; t--) {
                if (t <= NT-3) {              // prefetched tile: wait for it
                    if (t > 0) cp_wait<1>(); else cp_wait<0>();
                    __syncthreads();
                }
                const float* buf = xs + (t&1)*BUF_F;
                #pragma unroll 2
                for (int r = 0; r < 4; r++) {
                    const int srow = sl2*4 + r;
                    const float w0s = sc[g*1024 + (h0+0)*SS + t*TS + srow];
                    const float w1s = sc[g*1024 + (h0+1)*SS + t*TS + srow];
                    const u64 w0p = pack2(w0s, w0s);
                    const u64 w1p = pack2(w1s, w1s);
                    const u64x2* xr = (const u64x2*)(buf + srow*DD);
                    #pragma unroll
                    for (int m = 0; m < 4; m++) {
                        u64x2 xv = xr[lane + 32*m];
                        ua0[2*m+0] = ffma2(w0p, xv.x, ua0[2*m+0]);
                        ua0[2*m+1] = ffma2(w0p, xv.y, ua0[2*m+1]);
                        ua1[2*m+0] = ffma2(w1p, xv.x, ua1[2*m+0]);
                        ua1[2*m+1] = ffma2(w1p, xv.y, ua1[2*m+1]);
                    }
                }
                __syncthreads();    // done reading buf[t&1]
                if (t - 2 >= 0) {   // prefetch tile t-2 into the buffer just freed
                    float4* dst = xs4 + (t&1)*2048;
                    const float4* src = xb4 + (size_t)(t-2)*2048;
                    #pragma unroll
                    for (int i = 0; i < 4; i++) cp16(&dst[tid + 512*i], &src[tid + 512*i]);
                    cp_commit();
                }
            }

            // dump partials into xs scratch: [sl2][head][512]
            u64x2* xs2 = (u64x2*)xs;
            #pragma unroll
            for (int m = 0; m < 4; m++) {
                u64x2 t0; t0.x = ua0[2*m+0]; t0.y = ua0[2*m+1];
                u64x2 t1; t1.x = ua1[2*m+0]; t1.y = ua1[2*m+1];
                xs2[(sl2*8 + h0+0)*128 + lane + 32*m] = t0;
                xs2[(sl2*8 + h0+1)*128 + lane + 32*m] = t1;
            }
            __syncthreads();
            // reduce across the 4 s-slices -> u in qtu[g]
            for (int idx = tid; idx < NHH*128; idx += THREADS) {
                float4 s0 = xs4[0*1024 + idx];
                float4 s1 = xs4[1*1024 + idx];
                float4 s2 = xs4[2*1024 + idx];
                float4 s3 = xs4[3*1024 + idx];
                float4 r;
                r.x = (s0.x + s1.x) + (s2.x + s3.x);
                r.y = (s0.y + s1.y) + (s2.y + s3.y);
                r.z = (s0.z + s1.z) + (s2.z + s3.z);
                r.w = (s0.w + s1.w) + (s2.w + s3.w);
                qtu4[g*1024 + idx] = r;
            }
            __syncthreads();   // scratch consumed before next batch's priming
        }
    } // batches

    // ---- phase z: out[b_g][i] = Wv[i,:]·u[g][head(i)] + bv[i]  (warp w -> rows [w*32, w*32+32)) ----
    {
        const int zn = w >> 1;   // head for this warp's rows
        u64x2 ur[G][4];
        #pragma unroll
        for (int g = 0; g < G; g++)
            #pragma unroll
            for (int m = 0; m < 4; m++)
                ur[g][m] = qtu2[g*1024 + zn*128 + lane + 32*m];

        for (int r = 0; r < 32; r++) {
            const int i = w*32 + r;
            const u64x2* wrow = (const u64x2*)(Wv + (size_t)i*DD);
            u64 acc[G] = {0ull, 0ull, 0ull, 0ull};
            #pragma unroll
            for (int m = 0; m < 4; m++) {
                u64x2 wv = wrow[lane + 32*m];
                #pragma unroll
                for (int g = 0; g < G; g++) {
                    acc[g] = ffma2(wv.x, ur[g][m].x, acc[g]);
                    acc[g] = ffma2(wv.y, ur[g][m].y, acc[g]);
                }
            }
            float v = reduce4(hsum2(acc[0]), hsum2(acc[1]), hsum2(acc[2]), hsum2(acc[3]), lane);
            float bvi = __ldg(bv + i);
            if (lane < 4)
                out[(size_t)(b0 + lane)*DD + i] = v + bvi;
        }
    }
}

extern "C" void kernel_launch(void* const* d_in, const int* in_sizes, int n_in,
                              void* d_out, int out_size)
{
    const float* x_non = (const float*)d_in[0];
    const float* x_seq = (const float*)d_in[1];
    const int*   mask  = (const int*)  d_in[2];
    const float* Wq    = (const float*)d_in[3];
    const float* bq    = (const float*)d_in[4];
    const float* Wk    = (const float*)d_in[5];
    const float* bk    = (const float*)d_in[6];
    const float* Wv    = (const float*)d_in[7];
    const float* bv    = (const float*)d_in[8];
    float* out = (float*)d_out;

    const int smem_bytes = SMEM_F * (int)sizeof(float);   // ~152 KB
    cudaFuncSetAttribute(mha_kernel, cudaFuncAttributeMaxDynamicSharedMemorySize, smem_bytes);
    mha_kernel<<<1024/G, THREADS, smem_bytes>>>(x_non, x_seq, mask,
                                                Wq, bq, Wk, bk, Wv, bv, out);
}